// round 1
// baseline (speedup 1.0000x reference)
#include <cuda_runtime.h>
#include <math.h>

#define BB 128          // batch rows
#define DD 128          // feature dim
#define NMAX (1u<<20)   // memory slots
#define GRID2 1024      // pass-2 blocks

// -------- device scratch (statically allocated; no cudaMalloc anywhere) ----
__device__ float g_state[BB*DD];                   // normalized state [B][D]
__device__ float g_Z[BB];                          // softmax denominators
__device__ float g_E[(size_t)NMAX*BB];             // exp weights [N][B] (512 MB)
__device__ float g_WSpart[(size_t)GRID2*BB*DD];    // per-block WS partials (64 MB)

// ---------------------------------------------------------------------------
// K0: normalize encoded_state rows, zero Z.   <<<1,128>>>
// ---------------------------------------------------------------------------
__global__ void k_norm(const float* __restrict__ st) {
    int b = threadIdx.x;
    float ss = 0.f;
    #pragma unroll 8
    for (int d = 0; d < DD; ++d) { float v = st[b*DD + d]; ss += v*v; }
    float nrm = sqrtf(ss);
    float inv = 1.0f / fmaxf(nrm, 1e-12f);
    #pragma unroll 8
    for (int d = 0; d < DD; ++d) g_state[b*DD + d] = st[b*DD + d] * inv;
    g_Z[b] = 0.f;
}

// ---------------------------------------------------------------------------
// K1: per 128-key tile: S = K_tile . state^T  (contraction over D),
//     E = exp((S-1)*invT), store E[N][B], accumulate Z[b].
//     256 threads, 8x8 micro-tile: n_i = tn + 16*i, b_j = 8*tb + j.
// ---------------------------------------------------------------------------
__global__ void __launch_bounds__(256, 2)
k_pass1(const float* __restrict__ keys, float invT) {
    __shared__ float Ks[128][36];   // keys tile, 32-wide d-chunk, pad->stride 36
    __shared__ float Ss[128][36];   // state tile (same chunk)
    __shared__ float zsm[128];

    const int tid = threadIdx.x;
    const int tn  = tid & 15;       // n-lane
    const int tb  = tid >> 4;       // b-group (0..15)
    const size_t n0 = (size_t)blockIdx.x * 128;

    float acc[8][8];
    #pragma unroll
    for (int i = 0; i < 8; ++i)
        #pragma unroll
        for (int j = 0; j < 8; ++j) acc[i][j] = 0.f;

    for (int d0 = 0; d0 < DD; d0 += 32) {
        // cooperative load: 128 rows x 32 floats for each operand
        #pragma unroll
        for (int t = 0; t < 4; ++t) {
            int idx = tid + 256*t;            // 0..1023
            int row = idx >> 3;
            int c4  = idx & 7;
            float4 kv = *(const float4*)(keys + (n0 + row)*DD + d0 + c4*4);
            *(float4*)&Ks[row][c4*4] = kv;
            float4 sv = *(const float4*)(g_state + row*DD + d0 + c4*4);
            *(float4*)&Ss[row][c4*4] = sv;
        }
        __syncthreads();

        #pragma unroll 4
        for (int dd = 0; dd < 32; ++dd) {
            float kf[8], sf[8];
            #pragma unroll
            for (int i = 0; i < 8; ++i) kf[i] = Ks[tn + 16*i][dd];
            #pragma unroll
            for (int j = 0; j < 8; ++j) sf[j] = Ss[8*tb + j][dd];
            #pragma unroll
            for (int i = 0; i < 8; ++i)
                #pragma unroll
                for (int j = 0; j < 8; ++j)
                    acc[i][j] = fmaf(kf[i], sf[j], acc[i][j]);
        }
        __syncthreads();
    }

    // exp, partial Z, store E
    if (tid < 128) zsm[tid] = 0.f;
    __syncthreads();

    float zp[8];
    #pragma unroll
    for (int j = 0; j < 8; ++j) zp[j] = 0.f;
    #pragma unroll
    for (int i = 0; i < 8; ++i)
        #pragma unroll
        for (int j = 0; j < 8; ++j) {
            float e = __expf((acc[i][j] - 1.0f) * invT);  // logits <= 0 => e <= 1
            acc[i][j] = e;
            zp[j] += e;
        }
    #pragma unroll
    for (int j = 0; j < 8; ++j) atomicAdd(&zsm[8*tb + j], zp[j]);

    #pragma unroll
    for (int i = 0; i < 8; ++i) {
        size_t row = n0 + (size_t)(tn + 16*i);
        float4 v0 = make_float4(acc[i][0], acc[i][1], acc[i][2], acc[i][3]);
        float4 v1 = make_float4(acc[i][4], acc[i][5], acc[i][6], acc[i][7]);
        *(float4*)(g_E + row*BB + 8*tb    ) = v0;
        *(float4*)(g_E + row*BB + 8*tb + 4) = v1;
    }

    __syncthreads();
    if (tid < 128) atomicAdd(&g_Z[tid], zsm[tid]);
}

// ---------------------------------------------------------------------------
// K2: per block: chunk of n rows. W = E[n][b]/Z[b].
//     WSpart[b][d] += sum_n W * V[n][d];  new_age[n] = age[n] + sum_b W.
//     32-row tiles; 8x8 micro-tile: b_j = tbb + 16*j, d_l = tdd + 16*l.
// ---------------------------------------------------------------------------
__global__ void __launch_bounds__(256, 2)
k_pass2(const float* __restrict__ values, const float* __restrict__ age,
        float* __restrict__ out, int chunkN) {
    __shared__ float Es[32][132];
    __shared__ float Vs[32][132];
    __shared__ float zinv[128];
    __shared__ float napart[32][9];

    const int tid = threadIdx.x;
    if (tid < 128) zinv[tid] = 1.0f / g_Z[tid];
    __syncthreads();

    const int tbb = tid & 15;
    const int tdd = tid >> 4;
    const size_t base = (size_t)blockIdx.x * (size_t)chunkN;

    float acc[8][8];
    #pragma unroll
    for (int j = 0; j < 8; ++j)
        #pragma unroll
        for (int l = 0; l < 8; ++l) acc[j][l] = 0.f;

    for (int nt = 0; nt < chunkN; nt += 32) {
        const size_t n0 = base + nt;
        // load 32x128 of E (scaled by 1/Z) and V
        #pragma unroll
        for (int t = 0; t < 4; ++t) {
            int idx = tid + 256*t;           // 0..1023
            int row = idx >> 5;
            int c4  = idx & 31;
            float4 e = *(const float4*)(g_E + (n0 + row)*BB + c4*4);
            float4 z = *(const float4*)(&zinv[c4*4]);
            e.x *= z.x; e.y *= z.y; e.z *= z.z; e.w *= z.w;
            *(float4*)&Es[row][c4*4] = e;
            float4 v = *(const float4*)(values + (n0 + row)*DD + c4*4);
            *(float4*)&Vs[row][c4*4] = v;
        }
        __syncthreads();

        // new_age partial sums over b: 8 threads per row, 16 floats each
        {
            int r = tid & 31, q = tid >> 5;
            float s = 0.f;
            #pragma unroll
            for (int t = 0; t < 4; ++t) {
                float4 e = *(float4*)&Es[r][q*16 + t*4];
                s += (e.x + e.y) + (e.z + e.w);
            }
            napart[r][q] = s;
        }

        // rank-32 update
        #pragma unroll 4
        for (int n = 0; n < 32; ++n) {
            float ef[8], vf[8];
            #pragma unroll
            for (int j = 0; j < 8; ++j) ef[j] = Es[n][tbb + 16*j];
            #pragma unroll
            for (int l = 0; l < 8; ++l) vf[l] = Vs[n][tdd + 16*l];
            #pragma unroll
            for (int j = 0; j < 8; ++j)
                #pragma unroll
                for (int l = 0; l < 8; ++l)
                    acc[j][l] = fmaf(ef[j], vf[l], acc[j][l]);
        }
        __syncthreads();

        // finalize new_age for these 32 rows (napart written before the sync)
        if (tid < 32) {
            float s = 0.f;
            #pragma unroll
            for (int q = 0; q < 8; ++q) s += napart[tid][q];
            out[BB*DD + n0 + tid] = age[n0 + tid] + s;
        }
    }

    // write per-block WS partial (once)
    float* wp = g_WSpart + (size_t)blockIdx.x * (BB*DD);
    #pragma unroll
    for (int j = 0; j < 8; ++j)
        #pragma unroll
        for (int l = 0; l < 8; ++l)
            wp[(tbb + 16*j)*DD + (tdd + 16*l)] = acc[j][l];
}

// ---------------------------------------------------------------------------
// K3: reduce WS partials -> out[0 .. 16383]
// ---------------------------------------------------------------------------
__global__ void k_reduce(float* __restrict__ out, int nparts) {
    int i = blockIdx.x * blockDim.x + threadIdx.x;   // 16384 threads
    float s = 0.f;
    for (int k = 0; k < nparts; ++k)
        s += g_WSpart[(size_t)k * (BB*DD) + i];
    out[i] = s;
}

// ---------------------------------------------------------------------------
extern "C" void kernel_launch(void* const* d_in, const int* in_sizes, int n_in,
                              void* d_out, int out_size) {
    const float* st     = (const float*)d_in[0];   // [128,128]
    const float* keys   = (const float*)d_in[1];   // [N,128]
    const float* values = (const float*)d_in[2];   // [N,128]
    const float* age    = (const float*)d_in[3];   // [N]
    float* out = (float*)d_out;                    // [128*128 + N]

    const int N = in_sizes[3];
    double tt = 0.11 - log10((double)N) * 0.01;    // temperature (matches ref)
    float invT = (float)(1.0 / tt);

    k_norm<<<1, 128>>>(st);
    k_pass1<<<N / 128, 256>>>(keys, invT);
    int chunk = N / GRID2;                         // 1024 for N=2^20, mult of 32
    k_pass2<<<GRID2, 256>>>(values, age, out, chunk);
    k_reduce<<<(BB*DD) / 256, 256>>>(out, GRID2);
}